// round 14
// baseline (speedup 1.0000x reference)
#include <cuda_runtime.h>
#include <cuda_fp16.h>
#include <math.h>
#include <stdint.h>

#define NREL  500
#define BB    8192
#define KK    64
#define DIM   128
#define NTGT  20000
#define CAP   192
#define WSH   136   // W row stride in halves (272B; 16B-aligned rows)
#define HST   136
#define XST   132
#define CVTB  1250

__device__ float    g_mvec[BB][DIM];      // slot 0 = -time, 1.. = normalized nar
__device__ float    g_bh[BB];             // bias_h[u_idx[b]]
__device__ __half   g_tgt[NTGT * DIM];    // fp16 targets; time column zeroed
__device__ float2   g_tb[NTGT];           // {fp32 time, bias_t}

__device__ __forceinline__ float warp_sum(float p) {
    p += __shfl_xor_sync(0xffffffffu, p, 16);
    p += __shfl_xor_sync(0xffffffffu, p, 8);
    p += __shfl_xor_sync(0xffffffffu, p, 4);
    p += __shfl_xor_sync(0xffffffffu, p, 2);
    p += __shfl_xor_sync(0xffffffffu, p, 1);
    return p;
}

__device__ __forceinline__ uint32_t smem_u32(const void* p) {
    return (uint32_t)__cvta_generic_to_shared(p);
}

__device__ __forceinline__ void ldsm_x4(uint32_t& r0, uint32_t& r1,
                                        uint32_t& r2, uint32_t& r3, uint32_t a) {
    asm volatile("ldmatrix.sync.aligned.m8n8.x4.shared.b16 {%0,%1,%2,%3}, [%4];"
                 : "=r"(r0), "=r"(r1), "=r"(r2), "=r"(r3) : "r"(a));
}
__device__ __forceinline__ void ldsm_x2(uint32_t& r0, uint32_t& r1, uint32_t a) {
    asm volatile("ldmatrix.sync.aligned.m8n8.x2.shared.b16 {%0,%1}, [%2];"
                 : "=r"(r0), "=r"(r1) : "r"(a));
}
__device__ __forceinline__ void mma_16816(float& d0, float& d1, float& d2, float& d3,
                                          uint32_t a0, uint32_t a1, uint32_t a2, uint32_t a3,
                                          uint32_t b0, uint32_t b1) {
    asm volatile("mma.sync.aligned.m16n8k16.row.col.f32.f16.f16.f32 "
                 "{%0,%1,%2,%3}, {%4,%5,%6,%7}, {%8,%9}, {%0,%1,%2,%3};"
                 : "+f"(d0), "+f"(d1), "+f"(d2), "+f"(d3)
                 : "r"(a0), "r"(a1), "r"(a2), "r"(a3), "r"(b0), "r"(b1));
}

// ─── Kernel 1: blocks [0,NREL) HMMA matvec+normalize; rest convert targets ───
__global__ void __launch_bounds__(256, 4) hybo_matvec(
    const int*   __restrict__ u_idx,
    const int*   __restrict__ r_idx,
    const float* __restrict__ drug,
    const float* __restrict__ relb,
    const float* __restrict__ relW,
    const float* __restrict__ bias_h,
    const float* __restrict__ target,
    const float* __restrict__ bias_t)
{
    extern __shared__ __half Wsh[];                  // [128][WSH] halves (~34KB)
    __shared__ __align__(16) __half Hsh[16][HST];    // chunk heads, fp16
    __shared__ __align__(16) float  Xs[16][XST];     // chunk raw x, fp32
    __shared__ float rb[DIM];
    __shared__ int   list[CAP];
    __shared__ int   nmatch;

    const int tid = threadIdx.x;

    // ───────────── cvt path ─────────────
    if (blockIdx.x >= NREL) {
        const int c = blockIdx.x - NREL;
        #pragma unroll
        for (int j = 0; j < 2; j++) {
            int i = c * 512 + j * 256 + tid;         // float4 index
            if (i < NTGT * DIM / 4) {
                float4 v = ((const float4*)target)[i];
                if ((i & 31) == 0) {                 // first 4 floats of a row
                    int row = i >> 5;
                    g_tb[row] = make_float2(v.x, bias_t[row]);
                    v.x = 0.0f;                      // zero fp16 time slot
                }
                __half2* dst = (__half2*)g_tgt + 2 * i;
                dst[0] = __floats2half2_rn(v.x, v.y);
                dst[1] = __floats2half2_rn(v.z, v.w);
            }
        }
        return;
    }

    // ───────────── matvec path ─────────────
    const int r    = blockIdx.x;
    const int lane = tid & 31;
    const int warp = tid >> 5;

    if (tid == 0) nmatch = 0;

    {   // Stage W[r] fp32 -> fp16 SMEM; scan r_idx — independent, one barrier.
        const float4* Wg = (const float4*)(relW + (size_t)r * DIM * DIM);
        #pragma unroll
        for (int i4 = tid; i4 < DIM * DIM / 4; i4 += 256) {
            float4 w = Wg[i4];
            int e = i4 >> 5, d4 = i4 & 31;
            __half2* dst = (__half2*)(Wsh + e * WSH + d4 * 4);
            dst[0] = __floats2half2_rn(w.x, w.y);
            dst[1] = __floats2half2_rn(w.z, w.w);
        }
    }
    if (tid < DIM) rb[tid] = relb[r * DIM + tid];
    for (int b = tid; b < BB; b += 256) {
        if (r_idx[b] == r) {
            int p = atomicAdd(&nmatch, 1);
            if (p < CAP) list[p] = b;
        }
    }
    __syncthreads();
    const int n = (nmatch < CAP) ? nmatch : CAP;

    const uint32_t wBase = smem_u32(Wsh);
    const uint32_t hBase = smem_u32(Hsh);
    const int e0a = 16 * warp;
    const int e0b = e0a + 8;

    for (int base = 0; base < n; base += 16) {
        __syncthreads();   // protect Hsh/Xs from prior chunk's readers

        // Stage 2 head rows per warp (rows 2w, 2w+1), zero-fill invalid.
        int bI[2], uI[2];
        #pragma unroll
        for (int j = 0; j < 2; j++) {
            const int rr  = 2 * warp + j;
            const int idx = base + rr;
            const bool valid = (idx < n);
            bI[j] = valid ? list[idx] : -1;
            uI[j] = valid ? u_idx[bI[j]] : 0;
            float4 h = valid ? *(const float4*)(drug + (size_t)uI[j] * DIM + 4 * lane)
                             : make_float4(0.f, 0.f, 0.f, 0.f);
            __half2* d = (__half2*)(Hsh[rr] + 4 * lane);
            d[0] = __floats2half2_rn(h.x, h.y);
            d[1] = __floats2half2_rn(h.z, h.w);
        }
        __syncthreads();

        // HMMA: warp w computes x[0:16][16w : 16w+16), fp32 accum.
        float dA0 = 0.f, dA1 = 0.f, dA2 = 0.f, dA3 = 0.f;
        float dB0 = 0.f, dB1 = 0.f, dB2 = 0.f, dB3 = 0.f;
        const int l15  = lane & 15;
        const int brow = l15 & 7;
        const int bko  = (l15 >> 3) << 3;
        #pragma unroll
        for (int k = 0; k < 8; k++) {
            const int k0 = 16 * k;
            uint32_t a0, a1, a2, a3, b0, b1, b2, b3;
            ldsm_x4(a0, a1, a2, a3,
                    hBase + (uint32_t)(((lane & 15) * HST + k0 + ((lane >> 4) << 3)) << 1));
            ldsm_x2(b0, b1,
                    wBase + (uint32_t)(((e0a + brow) * WSH + k0 + bko) << 1));
            ldsm_x2(b2, b3,
                    wBase + (uint32_t)(((e0b + brow) * WSH + k0 + bko) << 1));
            mma_16816(dA0, dA1, dA2, dA3, a0, a1, a2, a3, b0, b1);
            mma_16816(dB0, dB1, dB2, dB3, a0, a1, a2, a3, b2, b3);
        }
        {   // Store fragments: lane l -> rows {l/4, l/4+8}, cols (l%4)*2.
            const int row0 = lane >> 2;
            const int c0   = (lane & 3) * 2;
            *(float2*)&Xs[row0    ][e0a + c0] = make_float2(dA0, dA1);
            *(float2*)&Xs[row0 + 8][e0a + c0] = make_float2(dA2, dA3);
            *(float2*)&Xs[row0    ][e0b + c0] = make_float2(dB0, dB1);
            *(float2*)&Xs[row0 + 8][e0b + c0] = make_float2(dB2, dB3);
        }
        __syncthreads();

        // Normalize + store: warp w handles its own rows 2w, 2w+1.
        #pragma unroll
        for (int j = 0; j < 2; j++) {
            const int rr = 2 * warp + j;
            if (base + rr >= n) break;
            const int bb = bI[j];
            const float x0   = Xs[rr][0];
            const float time = 2.5f / (1.0f + expf(-x0)) + 1.1f;
            float a0 = Xs[rr][lane]      + rb[lane];
            float a1 = Xs[rr][lane + 32] + rb[lane + 32];
            float a2 = Xs[rr][lane + 64] + rb[lane + 64];
            float a3 = Xs[rr][lane + 96] + rb[lane + 96];
            float s  = ((lane == 0) ? 0.0f : a0 * a0) + a1 * a1 + a2 * a2 + a3 * a3;
            s = warp_sum(s);
            const float scale = sqrtf((time * time - 1.0f) / s);
            g_mvec[bb][lane]      = (lane == 0) ? -time : a0 * scale;
            g_mvec[bb][lane + 32] = a1 * scale;
            g_mvec[bb][lane + 64] = a2 * scale;
            g_mvec[bb][lane + 96] = a3 * scale;
            if (lane == 0) g_bh[bb] = bias_h[uI[j]];
        }
    }
}

// ─── Kernel 2: scoring — 2 warps per item, 4-deep load pipeline ───
// Warp handles half = warp&1 of item b: ks [32*half, 32*half+32), 8 passes.
__global__ void hybo_score(
    const int*   __restrict__ v_idx,
    float*       __restrict__ out)
{
    __shared__ __align__(16) float mvs[8][DIM];

    const int tid  = threadIdx.x;
    const int lane = tid & 31;
    const int warp = tid >> 5;
    const int sub  = lane & 7;
    const int g    = lane >> 3;
    const int item = blockIdx.x * 4 + (warp >> 1);   // 4 items per block
    const int half = warp & 1;
    const int b    = item;

    // This warp's 32 target ids.
    const int vk = v_idx[b * KK + 32 * half + lane];

    ((float4*)mvs[warp])[lane] = ((const float4*)g_mvec[b])[lane];
    __syncwarp();

    const float4 ma = *(const float4*)(mvs[warp] + 8 * sub);
    const float4 mb = *(const float4*)(mvs[warp] + 8 * sub + 4);
    const float4 mc = *(const float4*)(mvs[warp] + 64 + 8 * sub);
    const float4 md = *(const float4*)(mvs[warp] + 64 + 8 * sub + 4);
    const __half2 mh0 = __floats2half2_rn(ma.x, ma.y);
    const __half2 mh1 = __floats2half2_rn(ma.z, ma.w);
    const __half2 mh2 = __floats2half2_rn(mb.x, mb.y);
    const __half2 mh3 = __floats2half2_rn(mb.z, mb.w);
    const __half2 mh4 = __floats2half2_rn(mc.x, mc.y);
    const __half2 mh5 = __floats2half2_rn(mc.z, mc.w);
    const __half2 mh6 = __floats2half2_rn(md.x, md.y);
    const __half2 mh7 = __floats2half2_rn(md.z, md.w);
    const float neg_time = mvs[warp][0];

    const float bh = g_bh[b];
    float* outb = out + b * KK + 32 * half;

    // 4-deep software pipeline over 8 passes.
    int4   pc0[4], pc1[4];
    float2 ptb[4];
    int    pv[4];

    #define LOAD_PASS(p)                                                     \
    {                                                                        \
        const int _v = __shfl_sync(0xffffffffu, vk, 4 * (p) + g);            \
        const int4* _row = (const int4*)(g_tgt + (size_t)_v * DIM);          \
        pv[(p) & 3]  = _v;                                                   \
        pc0[(p) & 3] = _row[sub];                                            \
        pc1[(p) & 3] = _row[8 + sub];                                        \
        ptb[(p) & 3] = (sub == 0) ? g_tb[_v] : make_float2(0.f, 0.f);        \
    }

    LOAD_PASS(0) LOAD_PASS(1) LOAD_PASS(2) LOAD_PASS(3)

    #pragma unroll
    for (int p = 0; p < 8; p++) {
        const int4   c0 = pc0[p & 3];
        const int4   c1 = pc1[p & 3];
        const float2 tb = ptb[p & 3];
        if (p + 4 < 8) LOAD_PASS(p + 4)

        __half2 a0 = __hmul2(*(const __half2*)&c0.x, mh0);
        a0 = __hfma2(*(const __half2*)&c0.y, mh1, a0);
        a0 = __hfma2(*(const __half2*)&c0.z, mh2, a0);
        a0 = __hfma2(*(const __half2*)&c0.w, mh3, a0);
        __half2 a1 = __hmul2(*(const __half2*)&c1.x, mh4);
        a1 = __hfma2(*(const __half2*)&c1.y, mh5, a1);
        a1 = __hfma2(*(const __half2*)&c1.z, mh6, a1);
        a1 = __hfma2(*(const __half2*)&c1.w, mh7, a1);

        const float2 ff = __half22float2(__hadd2(a0, a1));
        float acc = ff.x + ff.y;

        acc += __shfl_xor_sync(0xffffffffu, acc, 1);
        acc += __shfl_xor_sync(0xffffffffu, acc, 2);
        acc += __shfl_xor_sync(0xffffffffu, acc, 4);

        if (sub == 0)
            outb[4 * p + g] = 8.0f + 2.0f * (acc + neg_time * tb.x) + bh + tb.y;
    }
    #undef LOAD_PASS
}

extern "C" void kernel_launch(void* const* d_in, const int* in_sizes, int n_in,
                              void* d_out, int out_size) {
    const int*   u_idx  = (const int*)  d_in[0];
    const int*   r_idx  = (const int*)  d_in[1];
    const int*   v_idx  = (const int*)  d_in[2];
    const float* drug   = (const float*)d_in[3];
    const float* target = (const float*)d_in[4];
    const float* relb   = (const float*)d_in[5];
    const float* relW   = (const float*)d_in[6];
    const float* bias_h = (const float*)d_in[7];
    const float* bias_t = (const float*)d_in[8];
    float*       out    = (float*)d_out;

    static bool attr_done = false;
    if (!attr_done) {
        cudaFuncSetAttribute(hybo_matvec,
                             cudaFuncAttributeMaxDynamicSharedMemorySize,
                             DIM * WSH * sizeof(__half));
        attr_done = true;
    }

    hybo_matvec<<<NREL + CVTB, 256, DIM * WSH * sizeof(__half)>>>(
        u_idx, r_idx, drug, relb, relW, bias_h, target, bias_t);
    hybo_score<<<BB / 4, 256>>>(v_idx, out);
}

// round 15
// speedup vs baseline: 1.0767x; 1.0767x over previous
#include <cuda_runtime.h>
#include <cuda_fp16.h>
#include <math.h>
#include <stdint.h>

#define NREL  500
#define BB    8192
#define KK    64
#define DIM   128
#define NTGT  20000
#define CAP   192
#define WSH   136   // W row stride in halves (272B; 16B-aligned rows)
#define HST   136   // head row stride in halves
#define XST   132   // X row stride in floats
#define CHUNK 32
#define CVTB  1250

__device__ float    g_mvec[BB][DIM];      // slot 0 = -time, 1.. = normalized nar
__device__ float    g_bh[BB];             // bias_h[u_idx[b]]
__device__ __half   g_tgt[NTGT * DIM];    // fp16 targets; time column zeroed
__device__ float2   g_tb[NTGT];           // {fp32 time, bias_t}

__device__ __forceinline__ float warp_sum(float p) {
    p += __shfl_xor_sync(0xffffffffu, p, 16);
    p += __shfl_xor_sync(0xffffffffu, p, 8);
    p += __shfl_xor_sync(0xffffffffu, p, 4);
    p += __shfl_xor_sync(0xffffffffu, p, 2);
    p += __shfl_xor_sync(0xffffffffu, p, 1);
    return p;
}

__device__ __forceinline__ uint32_t smem_u32(const void* p) {
    return (uint32_t)__cvta_generic_to_shared(p);
}

__device__ __forceinline__ void ldsm_x4(uint32_t& r0, uint32_t& r1,
                                        uint32_t& r2, uint32_t& r3, uint32_t a) {
    asm volatile("ldmatrix.sync.aligned.m8n8.x4.shared.b16 {%0,%1,%2,%3}, [%4];"
                 : "=r"(r0), "=r"(r1), "=r"(r2), "=r"(r3) : "r"(a));
}
__device__ __forceinline__ void ldsm_x2(uint32_t& r0, uint32_t& r1, uint32_t a) {
    asm volatile("ldmatrix.sync.aligned.m8n8.x2.shared.b16 {%0,%1}, [%2];"
                 : "=r"(r0), "=r"(r1) : "r"(a));
}
__device__ __forceinline__ void mma_16816(float& d0, float& d1, float& d2, float& d3,
                                          uint32_t a0, uint32_t a1, uint32_t a2, uint32_t a3,
                                          uint32_t b0, uint32_t b1) {
    asm volatile("mma.sync.aligned.m16n8k16.row.col.f32.f16.f16.f32 "
                 "{%0,%1,%2,%3}, {%4,%5,%6,%7}, {%8,%9}, {%0,%1,%2,%3};"
                 : "+f"(d0), "+f"(d1), "+f"(d2), "+f"(d3)
                 : "r"(a0), "r"(a1), "r"(a2), "r"(a3), "r"(b0), "r"(b1));
}

// ─── Kernel 1: blocks [0,NREL) HMMA matvec+normalize; rest convert targets ───
__global__ void __launch_bounds__(256, 4) hybo_matvec(
    const int*   __restrict__ u_idx,
    const int*   __restrict__ r_idx,
    const float* __restrict__ drug,
    const float* __restrict__ relb,
    const float* __restrict__ relW,
    const float* __restrict__ bias_h,
    const float* __restrict__ target,
    const float* __restrict__ bias_t)
{
    extern __shared__ __half Wsh[];                     // [128][WSH] (~34KB)
    // Hsh (chunk heads, fp16) and Xs (chunk raw x, fp32) alias one buffer:
    // Hsh is dead after the last ldmatrix; Xs written after a barrier.
    __shared__ __align__(16) char uni[CHUNK * XST * 4]; // 16.9KB
    __shared__ float rb[DIM];
    __shared__ int   list[CAP];
    __shared__ int   nmatch;

    __half (*Hsh)[HST] = (__half(*)[HST])uni;
    float  (*Xs)[XST]  = (float(*)[XST])uni;

    const int tid = threadIdx.x;

    // ───────────── cvt path ─────────────
    if (blockIdx.x >= NREL) {
        const int c = blockIdx.x - NREL;
        #pragma unroll
        for (int j = 0; j < 2; j++) {
            int i = c * 512 + j * 256 + tid;         // float4 index
            if (i < NTGT * DIM / 4) {
                float4 v = ((const float4*)target)[i];
                if ((i & 31) == 0) {                 // first 4 floats of a row
                    int row = i >> 5;
                    g_tb[row] = make_float2(v.x, bias_t[row]);
                    v.x = 0.0f;                      // zero fp16 time slot
                }
                __half2* dst = (__half2*)g_tgt + 2 * i;
                dst[0] = __floats2half2_rn(v.x, v.y);
                dst[1] = __floats2half2_rn(v.z, v.w);
            }
        }
        return;
    }

    // ───────────── matvec path ─────────────
    const int r    = blockIdx.x;
    const int lane = tid & 31;
    const int warp = tid >> 5;

    if (tid == 0) nmatch = 0;

    {   // Stage W[r] fp32 -> fp16 SMEM; int4 scan of r_idx — one barrier.
        const float4* Wg = (const float4*)(relW + (size_t)r * DIM * DIM);
        #pragma unroll
        for (int i4 = tid; i4 < DIM * DIM / 4; i4 += 256) {
            float4 w = Wg[i4];
            int e = i4 >> 5, d4 = i4 & 31;
            __half2* dst = (__half2*)(Wsh + e * WSH + d4 * 4);
            dst[0] = __floats2half2_rn(w.x, w.y);
            dst[1] = __floats2half2_rn(w.z, w.w);
        }
    }
    if (tid < DIM) rb[tid] = relb[r * DIM + tid];
    {
        const int4* r4 = (const int4*)r_idx;
        #pragma unroll
        for (int j = tid; j < BB / 4; j += 256) {
            const int4 v = r4[j];
            if (v.x == r) { int p = atomicAdd(&nmatch, 1); if (p < CAP) list[p] = 4 * j; }
            if (v.y == r) { int p = atomicAdd(&nmatch, 1); if (p < CAP) list[p] = 4 * j + 1; }
            if (v.z == r) { int p = atomicAdd(&nmatch, 1); if (p < CAP) list[p] = 4 * j + 2; }
            if (v.w == r) { int p = atomicAdd(&nmatch, 1); if (p < CAP) list[p] = 4 * j + 3; }
        }
    }
    __syncthreads();
    const int n = (nmatch < CAP) ? nmatch : CAP;

    const uint32_t wBase = smem_u32(Wsh);
    const uint32_t hBase = smem_u32(uni);
    const int e0a = 16 * warp;
    const int e0b = e0a + 8;

    for (int base = 0; base < n; base += CHUNK) {
        __syncthreads();   // prior chunk's Xs readers done before Hsh restage

        // Stage 4 head rows per warp (rows 4w..4w+3), zero-fill invalid.
        int bI[4], uI[4];
        #pragma unroll
        for (int j = 0; j < 4; j++) {
            const int rr  = 4 * warp + j;
            const int idx = base + rr;
            const bool valid = (idx < n);
            bI[j] = valid ? list[idx] : -1;
            uI[j] = valid ? u_idx[bI[j]] : 0;
            float4 h = valid ? *(const float4*)(drug + (size_t)uI[j] * DIM + 4 * lane)
                             : make_float4(0.f, 0.f, 0.f, 0.f);
            __half2* d = (__half2*)(Hsh[rr] + 4 * lane);
            d[0] = __floats2half2_rn(h.x, h.y);
            d[1] = __floats2half2_rn(h.z, h.w);
        }
        __syncthreads();

        // HMMA: warp w computes x[0:32][16w : 16w+16), fp32 accum.
        float d00 = 0.f, d01 = 0.f, d02 = 0.f, d03 = 0.f;   // rows 0-15,  e0a
        float d10 = 0.f, d11 = 0.f, d12 = 0.f, d13 = 0.f;   // rows 0-15,  e0b
        float d20 = 0.f, d21 = 0.f, d22 = 0.f, d23 = 0.f;   // rows 16-31, e0a
        float d30 = 0.f, d31 = 0.f, d32 = 0.f, d33 = 0.f;   // rows 16-31, e0b
        const int l15  = lane & 15;
        const int brow = l15 & 7;
        const int bko  = (l15 >> 3) << 3;
        #pragma unroll
        for (int k = 0; k < 8; k++) {
            const int k0 = 16 * k;
            uint32_t a0, a1, a2, a3, c0, c1, c2, c3, b0, b1, b2, b3;
            ldsm_x4(a0, a1, a2, a3,
                    hBase + (uint32_t)((((lane & 15)     ) * HST + k0 + ((lane >> 4) << 3)) << 1));
            ldsm_x4(c0, c1, c2, c3,
                    hBase + (uint32_t)((((lane & 15) + 16) * HST + k0 + ((lane >> 4) << 3)) << 1));
            ldsm_x2(b0, b1, wBase + (uint32_t)(((e0a + brow) * WSH + k0 + bko) << 1));
            ldsm_x2(b2, b3, wBase + (uint32_t)(((e0b + brow) * WSH + k0 + bko) << 1));
            mma_16816(d00, d01, d02, d03, a0, a1, a2, a3, b0, b1);
            mma_16816(d10, d11, d12, d13, a0, a1, a2, a3, b2, b3);
            mma_16816(d20, d21, d22, d23, c0, c1, c2, c3, b0, b1);
            mma_16816(d30, d31, d32, d33, c0, c1, c2, c3, b2, b3);
        }
        __syncthreads();   // all ldmatrix reads of Hsh done before Xs overwrite

        {   // Store fragments: lane l -> rows {l/4, l/4+8}, cols (l%4)*2.
            const int row0 = lane >> 2;
            const int c0   = (lane & 3) * 2;
            *(float2*)&Xs[row0     ][e0a + c0] = make_float2(d00, d01);
            *(float2*)&Xs[row0 + 8 ][e0a + c0] = make_float2(d02, d03);
            *(float2*)&Xs[row0     ][e0b + c0] = make_float2(d10, d11);
            *(float2*)&Xs[row0 + 8 ][e0b + c0] = make_float2(d12, d13);
            *(float2*)&Xs[row0 + 16][e0a + c0] = make_float2(d20, d21);
            *(float2*)&Xs[row0 + 24][e0a + c0] = make_float2(d22, d23);
            *(float2*)&Xs[row0 + 16][e0b + c0] = make_float2(d30, d31);
            *(float2*)&Xs[row0 + 24][e0b + c0] = make_float2(d32, d33);
        }
        __syncthreads();

        // Normalize + store: warp w handles rows 4w..4w+3.
        #pragma unroll
        for (int j = 0; j < 4; j++) {
            const int rr = 4 * warp + j;
            if (base + rr >= n) break;
            const int bb = bI[j];
            const float x0   = Xs[rr][0];
            const float time = 2.5f / (1.0f + expf(-x0)) + 1.1f;
            float a0 = Xs[rr][lane]      + rb[lane];
            float a1 = Xs[rr][lane + 32] + rb[lane + 32];
            float a2 = Xs[rr][lane + 64] + rb[lane + 64];
            float a3 = Xs[rr][lane + 96] + rb[lane + 96];
            float s  = ((lane == 0) ? 0.0f : a0 * a0) + a1 * a1 + a2 * a2 + a3 * a3;
            s = warp_sum(s);
            const float scale = sqrtf((time * time - 1.0f) / s);
            g_mvec[bb][lane]      = (lane == 0) ? -time : a0 * scale;
            g_mvec[bb][lane + 32] = a1 * scale;
            g_mvec[bb][lane + 64] = a2 * scale;
            g_mvec[bb][lane + 96] = a3 * scale;
            if (lane == 0) g_bh[bb] = bias_h[uI[j]];
        }
    }
}

// ─── Kernel 2: scoring — octet gather + HFMA2 (R13 version, near L2-BW cap) ──
__global__ void __launch_bounds__(256) hybo_score(
    const int*   __restrict__ v_idx,
    float*       __restrict__ out)
{
    __shared__ __align__(16) float mvs[8][DIM];

    const int tid  = threadIdx.x;
    const int lane = tid & 31;
    const int warp = tid >> 5;
    const int sub  = lane & 7;
    const int g    = lane >> 3;
    const int b    = blockIdx.x * 8 + warp;

    const int vk0 = v_idx[b * KK + lane];
    const int vk1 = v_idx[b * KK + 32 + lane];

    ((float4*)mvs[warp])[lane] = ((const float4*)g_mvec[b])[lane];
    __syncwarp();

    const float4 ma = *(const float4*)(mvs[warp] + 8 * sub);
    const float4 mb = *(const float4*)(mvs[warp] + 8 * sub + 4);
    const float4 mc = *(const float4*)(mvs[warp] + 64 + 8 * sub);
    const float4 md = *(const float4*)(mvs[warp] + 64 + 8 * sub + 4);
    const __half2 mh0 = __floats2half2_rn(ma.x, ma.y);
    const __half2 mh1 = __floats2half2_rn(ma.z, ma.w);
    const __half2 mh2 = __floats2half2_rn(mb.x, mb.y);
    const __half2 mh3 = __floats2half2_rn(mb.z, mb.w);
    const __half2 mh4 = __floats2half2_rn(mc.x, mc.y);
    const __half2 mh5 = __floats2half2_rn(mc.z, mc.w);
    const __half2 mh6 = __floats2half2_rn(md.x, md.y);
    const __half2 mh7 = __floats2half2_rn(md.z, md.w);
    const float neg_time = mvs[warp][0];

    const float bh = g_bh[b];
    float* outb = out + b * KK;

    #pragma unroll
    for (int p = 0; p < 16; p++) {
        const int k = 4 * p + g;
        const int v = (p < 8) ? __shfl_sync(0xffffffffu, vk0, 4 * p + g)
                              : __shfl_sync(0xffffffffu, vk1, 4 * (p - 8) + g);
        const int4* row = (const int4*)(g_tgt + (size_t)v * DIM);
        float2 tb = make_float2(0.0f, 0.0f);
        if (sub == 0) tb = g_tb[v];               // {fp32 time, bias_t}

        const int4 c0 = row[sub];       // halves [8*sub, +8)  (slot0 zeroed)
        const int4 c1 = row[8 + sub];   // halves [64 + 8*sub, +8)

        __half2 a0 = __hmul2(*(const __half2*)&c0.x, mh0);
        a0 = __hfma2(*(const __half2*)&c0.y, mh1, a0);
        a0 = __hfma2(*(const __half2*)&c0.z, mh2, a0);
        a0 = __hfma2(*(const __half2*)&c0.w, mh3, a0);
        __half2 a1 = __hmul2(*(const __half2*)&c1.x, mh4);
        a1 = __hfma2(*(const __half2*)&c1.y, mh5, a1);
        a1 = __hfma2(*(const __half2*)&c1.z, mh6, a1);
        a1 = __hfma2(*(const __half2*)&c1.w, mh7, a1);

        const float2 ff = __half22float2(__hadd2(a0, a1));
        float acc = ff.x + ff.y;

        acc += __shfl_xor_sync(0xffffffffu, acc, 1);
        acc += __shfl_xor_sync(0xffffffffu, acc, 2);
        acc += __shfl_xor_sync(0xffffffffu, acc, 4);

        if (sub == 0)
            outb[k] = 8.0f + 2.0f * (acc + neg_time * tb.x) + bh + tb.y;
    }
}

extern "C" void kernel_launch(void* const* d_in, const int* in_sizes, int n_in,
                              void* d_out, int out_size) {
    const int*   u_idx  = (const int*)  d_in[0];
    const int*   r_idx  = (const int*)  d_in[1];
    const int*   v_idx  = (const int*)  d_in[2];
    const float* drug   = (const float*)d_in[3];
    const float* target = (const float*)d_in[4];
    const float* relb   = (const float*)d_in[5];
    const float* relW   = (const float*)d_in[6];
    const float* bias_h = (const float*)d_in[7];
    const float* bias_t = (const float*)d_in[8];
    float*       out    = (float*)d_out;

    static bool attr_done = false;
    if (!attr_done) {
        cudaFuncSetAttribute(hybo_matvec,
                             cudaFuncAttributeMaxDynamicSharedMemorySize,
                             DIM * WSH * sizeof(__half));
        attr_done = true;
    }

    hybo_matvec<<<NREL + CVTB, 256, DIM * WSH * sizeof(__half)>>>(
        u_idx, r_idx, drug, relb, relW, bias_h, target, bias_t);
    hybo_score<<<BB / 8, 256>>>(v_idx, out);
}